// round 1
// baseline (speedup 1.0000x reference)
#include <cuda_runtime.h>
#include <math.h>

// SimpleAttention: O = softmax(X X^T + masks) X, B=4 S=2048 D=1024 fp32.
// Flash-style streaming over key tiles; fp32 FFMA baseline.

namespace {

constexpr int B = 4;
constexpr int S = 2048;
constexpr int D = 1024;
constexpr int M = 16;        // queries per CTA
constexpr int NK = 32;       // keys per tile
constexpr int THREADS = 256;
constexpr float NEGINF = -1.0e9f;

constexpr int SMEM_K_FLOATS = NK * D;                       // 32768
constexpr int SMEM_FLOATS = SMEM_K_FLOATS + 2 * M * NK + 3 * M;
constexpr int SMEM_BYTES = SMEM_FLOATS * 4;                 // 135360

// 128B-period XOR swizzle on within-row byte offsets (multiples of 16).
__device__ __forceinline__ int swz(int off) {
    return off ^ (((off >> 8) & 7) << 4);
}

__global__ void __launch_bounds__(THREADS, 1)
attn_fp32_kernel(const float* __restrict__ X, const int* __restrict__ mask,
                 float* __restrict__ O)
{
    extern __shared__ float sm[];
    float* Ks   = sm;                         // [NK][D] swizzled
    float* Ss   = sm + SMEM_K_FLOATS;         // [M][NK] raw scores
    float* Ps   = Ss + M * NK;                // [M][NK] probs
    float* rmax = Ps + M * NK;                // [M]
    float* rsum = rmax + M;                   // [M]
    float* ralp = rsum + M;                   // [M]

    const int t = threadIdx.x;
    const int w = t >> 5;        // warp 0..7
    const int c = t & 31;        // lane = 32-float d-chunk index

    // balance causal work across waves: pair small and large q-tiles
    const int bx = blockIdx.x;
    const int qt = (bx & 1) ? (S / M - 1 - (bx >> 1)) : (bx >> 1);
    const int qbase = qt * M;
    const int b = blockIdx.y;

    const int mA = w, mB = w + 8;
    const int qA = qbase + mA, qB = qbase + mB;

    const float* Xb = X + (size_t)b * S * D;
    const int*   mb = mask + b * S;

    // Q rows resident in registers (2 rows x 32 floats), O accumulators likewise
    float Qa[32], Qb[32], accA[32], accB[32];
    {
        const float4* pa = reinterpret_cast<const float4*>(Xb + (size_t)qA * D + c * 32);
        const float4* pb = reinterpret_cast<const float4*>(Xb + (size_t)qB * D + c * 32);
        #pragma unroll
        for (int j = 0; j < 8; ++j) {
            float4 va = pa[j];
            float4 vb = pb[j];
            Qa[4*j] = va.x; Qa[4*j+1] = va.y; Qa[4*j+2] = va.z; Qa[4*j+3] = va.w;
            Qb[4*j] = vb.x; Qb[4*j+1] = vb.y; Qb[4*j+2] = vb.z; Qb[4*j+3] = vb.w;
        }
    }
    #pragma unroll
    for (int j = 0; j < 32; ++j) { accA[j] = 0.f; accB[j] = 0.f; }

    if (t < M) { rmax[t] = -3.0e38f; rsum[t] = 0.f; }
    __syncthreads();

    const int ntiles = (qbase + M + NK - 1) / NK;

    for (int tile = 0; tile < ntiles; ++tile) {
        const int kb = tile * NK;

        // ---- load K tile (also serves as V) into swizzled smem ----
        {
            const int r  = t >> 3;     // 0..31 key row
            const int s8 = t & 7;
            const float* kp = Xb + (size_t)(kb + r) * D;
            char* drow = (char*)(Ks + r * D);
            #pragma unroll
            for (int i = 0; i < 32; ++i) {
                int off = s8 * 16 + i * 128;   // byte offset within row
                float4 v = *reinterpret_cast<const float4*>(kp + (off >> 2));
                *reinterpret_cast<float4*>(drow + swz(off)) = v;
            }
        }
        __syncthreads();

        // ---- QK^T: each thread does partial dot over its 32-d chunk for 2 rows ----
        for (int n = 0; n < NK; ++n) {
            const char* krow = (const char*)(Ks + n * D);
            float a0 = 0.f, a1 = 0.f, a2 = 0.f, a3 = 0.f;
            float b0 = 0.f, b1 = 0.f, b2 = 0.f, b3 = 0.f;
            #pragma unroll
            for (int j = 0; j < 8; ++j) {
                int off = c * 128 + j * 16;
                float4 v = *reinterpret_cast<const float4*>(krow + swz(off));
                a0 += Qa[4*j  ] * v.x;  b0 += Qb[4*j  ] * v.x;
                a1 += Qa[4*j+1] * v.y;  b1 += Qb[4*j+1] * v.y;
                a2 += Qa[4*j+2] * v.z;  b2 += Qb[4*j+2] * v.z;
                a3 += Qa[4*j+3] * v.w;  b3 += Qb[4*j+3] * v.w;
            }
            float pA = (a0 + a1) + (a2 + a3);
            float pB = (b0 + b1) + (b2 + b3);
            #pragma unroll
            for (int d = 16; d > 0; d >>= 1) {
                pA += __shfl_xor_sync(0xffffffffu, pA, d);
                pB += __shfl_xor_sync(0xffffffffu, pB, d);
            }
            if (c == 0) {
                Ss[mA * NK + n] = pA;
                Ss[mB * NK + n] = pB;
            }
        }
        __syncthreads();

        // ---- online softmax update (one thread per query row) ----
        if (t < M) {
            const int qq = qbase + t;
            const float oldmx = rmax[t];
            float mx = oldmx;
            #pragma unroll
            for (int n = 0; n < NK; ++n) {
                float v = Ss[t * NK + n];
                const int k = kb + n;
                if (k > qq)      v += NEGINF;   // causal
                if (mb[k] == 0)  v += NEGINF;   // padding
                Ss[t * NK + n] = v;
                mx = fmaxf(mx, v);
            }
            const float al = expf(oldmx - mx);  // 0 on first tile (underflow)
            float sum = 0.f;
            #pragma unroll
            for (int n = 0; n < NK; ++n) {
                float p = expf(Ss[t * NK + n] - mx);
                Ps[t * NK + n] = p;
                sum += p;
            }
            rsum[t] = rsum[t] * al + sum;
            rmax[t] = mx;
            ralp[t] = al;
        }
        __syncthreads();

        // ---- PV: rescale accumulators, add P * V (V == K tile) ----
        {
            const float aA = ralp[mA];
            const float aB = ralp[mB];
            #pragma unroll
            for (int j = 0; j < 32; ++j) { accA[j] *= aA; accB[j] *= aB; }

            for (int n = 0; n < NK; ++n) {
                const float pA = Ps[mA * NK + n];
                const float pB = Ps[mB * NK + n];
                const char* krow = (const char*)(Ks + n * D);
                #pragma unroll
                for (int j = 0; j < 8; ++j) {
                    int off = c * 128 + j * 16;
                    float4 v = *reinterpret_cast<const float4*>(krow + swz(off));
                    accA[4*j  ] += pA * v.x;  accB[4*j  ] += pB * v.x;
                    accA[4*j+1] += pA * v.y;  accB[4*j+1] += pB * v.y;
                    accA[4*j+2] += pA * v.z;  accB[4*j+2] += pB * v.z;
                    accA[4*j+3] += pA * v.w;  accB[4*j+3] += pB * v.w;
                }
            }
        }
        __syncthreads();   // before next tile overwrites Ks
    }

    // ---- finalize and store ----
    const float iA = 1.0f / rsum[mA];
    const float iB = 1.0f / rsum[mB];
    float4* oA = reinterpret_cast<float4*>(O + ((size_t)b * S + qA) * D + c * 32);
    float4* oB = reinterpret_cast<float4*>(O + ((size_t)b * S + qB) * D + c * 32);
    #pragma unroll
    for (int j = 0; j < 8; ++j) {
        oA[j] = make_float4(accA[4*j] * iA, accA[4*j+1] * iA,
                            accA[4*j+2] * iA, accA[4*j+3] * iA);
        oB[j] = make_float4(accB[4*j] * iB, accB[4*j+1] * iB,
                            accB[4*j+2] * iB, accB[4*j+3] * iB);
    }
}

} // namespace

extern "C" void kernel_launch(void* const* d_in, const int* in_sizes, int n_in,
                              void* d_out, int out_size)
{
    const float* X    = (const float*)d_in[0];
    const int*   mask = (const int*)d_in[1];
    float*       O    = (float*)d_out;

    cudaFuncSetAttribute(attn_fp32_kernel,
                         cudaFuncAttributeMaxDynamicSharedMemorySize, SMEM_BYTES);
    attn_fp32_kernel<<<dim3(S / M, B), THREADS, SMEM_BYTES>>>(X, mask, O);
}

// round 3
// speedup vs baseline: 6.0010x; 6.0010x over previous
#include <cuda_runtime.h>
#include <cuda_bf16.h>
#include <math.h>
#include <stdint.h>

// SimpleAttention B=4 S=2048 D=1024 fp32.
// bf16 hi/lo split fp32-emulated GEMMs on mma.sync (HMMA, non-'a' ISA — the
// harness compiles at compute_100 where tcgen05 is unavailable).
// K1: split X -> bf16 hi/lo + transposed copies
// K2: S = X X^T, 128x128 tiles, causal tiles only
// K3: row softmax -> normalized P as bf16 hi/lo (zero-padded to tile bound)
// K4: O = P X with causal K truncation

namespace {

constexpr int B = 4, S = 2048, D = 1024;
constexpr float NEGV = -1.0e9f;

__device__ __align__(16) __nv_bfloat16 g_Xhi [(size_t)B * S * D];
__device__ __align__(16) __nv_bfloat16 g_Xlo [(size_t)B * S * D];
__device__ __align__(16) __nv_bfloat16 g_XThi[(size_t)B * D * S];
__device__ __align__(16) __nv_bfloat16 g_XTlo[(size_t)B * D * S];
__device__ __align__(16) float         g_S   [(size_t)B * S * S];
__device__ __align__(16) __nv_bfloat16 g_Phi [(size_t)B * S * S];
__device__ __align__(16) __nv_bfloat16 g_Plo [(size_t)B * S * S];

// ---------------- ptx helpers (non-'a' ISA only) ------------------------------
__device__ __forceinline__ uint32_t smem_u32(const void* p) {
    uint32_t a;
    asm("{ .reg .u64 t; cvta.to.shared.u64 t, %1; cvt.u32.u64 %0, t; }" : "=r"(a) : "l"(p));
    return a;
}
__device__ __forceinline__ void cpa16(uint32_t dst, const void* src) {
    asm volatile("cp.async.cg.shared.global [%0], [%1], 16;" :: "r"(dst), "l"(src) : "memory");
}
__device__ __forceinline__ void cpa_commit() {
    asm volatile("cp.async.commit_group;" ::: "memory");
}
template <int N> __device__ __forceinline__ void cpa_wait() {
    asm volatile("cp.async.wait_group %0;" :: "n"(N) : "memory");
}
__device__ __forceinline__ void ldm4(uint32_t* r, uint32_t addr) {
    asm volatile("ldmatrix.sync.aligned.m8n8.x4.shared.b16 {%0,%1,%2,%3}, [%4];"
                 : "=r"(r[0]), "=r"(r[1]), "=r"(r[2]), "=r"(r[3]) : "r"(addr));
}
__device__ __forceinline__ void mma_bf16(float* c, const uint32_t* a, const uint32_t* b) {
    asm volatile(
        "mma.sync.aligned.m16n8k16.row.col.f32.bf16.bf16.f32 "
        "{%0,%1,%2,%3}, {%4,%5,%6,%7}, {%8,%9}, {%0,%1,%2,%3};"
        : "+f"(c[0]), "+f"(c[1]), "+f"(c[2]), "+f"(c[3])
        : "r"(a[0]), "r"(a[1]), "r"(a[2]), "r"(a[3]), "r"(b[0]), "r"(b[1]));
}

// ---------------- GEMM core ---------------------------------------------------
// C[128,128] = (Ahi+Alo)[128,K] * (Bhi+Blo)[128,K]^T, lo*lo dropped.
// 8 warps as 4(m) x 2(n); warp tile 32x64; K-chunk 32.
constexpr int KP = 40;                      // padded row stride in bf16 elems (80B)
constexpr int ARR_BYTES = 128 * KP * 2;     // 10240
constexpr int STAGE_BYTES = 4 * ARR_BYTES;  // 40960: Ah, Al, Bh, Bl
constexpr int SMEM_GEMM = 2 * STAGE_BYTES;  // 81920

__device__ __forceinline__ void load_chunk(
    uint32_t stage_base,
    const __nv_bfloat16* Ah, const __nv_bfloat16* Al,
    const __nv_bfloat16* Bh, const __nv_bfloat16* Bl,
    int strideA, int strideB, int t)
{
#pragma unroll
    for (int j = 0; j < 8; ++j) {
        const int s = t + j * 256;           // 0..2047
        const int arr = s >> 9;              // 0..3
        const int rem = s & 511;
        const int row = rem >> 2;            // 0..127
        const int seg = rem & 3;             // 16B segment
        const __nv_bfloat16* base = (arr == 0) ? Ah : (arr == 1) ? Al : (arr == 2) ? Bh : Bl;
        const int stride = (arr < 2) ? strideA : strideB;
        cpa16(stage_base + arr * ARR_BYTES + row * (KP * 2) + seg * 16,
              base + (size_t)row * stride + seg * 8);
    }
}

__device__ __forceinline__ void gemm_core(
    const __nv_bfloat16* Ah, const __nv_bfloat16* Al,
    const __nv_bfloat16* Bh, const __nv_bfloat16* Bl,
    int strideA, int strideB, int nch,
    float* out, int ostride,
    char* sm, int t)
{
    const uint32_t smb = smem_u32(sm);
    const int w = t >> 5, l = t & 31;
    const int wm = w >> 1, wn = w & 1;       // 4 x 2 warps

    float acc[2][8][4];
#pragma unroll
    for (int i = 0; i < 2; ++i)
#pragma unroll
        for (int j = 0; j < 8; ++j)
#pragma unroll
            for (int k = 0; k < 4; ++k) acc[i][j][k] = 0.f;

    // per-lane ldmatrix base offsets (within an array, bytes)
    // A: row = wm*32 + f*16 + (l&15), col = kk*16 + (l>>4)*8
    const int a_row = wm * 32 + (l & 15);
    const int a_col = (l >> 4) << 3;
    // B: row n = wn*64 + pair*16 + (l&7) + ((l>>4)&1)*8, col = kk*16 + ((l>>3)&1)*8
    const int b_row = wn * 64 + (l & 7) + (((l >> 4) & 1) << 3);
    const int b_col = ((l >> 3) & 1) << 3;

    load_chunk(smb, Ah, Al, Bh, Bl, strideA, strideB, t);
    cpa_commit();

    for (int i = 0; i < nch; ++i) {
        cpa_wait<0>();
        __syncthreads();                     // chunk i visible; prev stage free
        if (i + 1 < nch) {
            load_chunk(smb + (((i + 1) & 1) ? STAGE_BYTES : 0),
                       Ah + (i + 1) * 32, Al + (i + 1) * 32,
                       Bh + (i + 1) * 32, Bl + (i + 1) * 32,
                       strideA, strideB, t);
            cpa_commit();
        }
        const uint32_t sb = smb + ((i & 1) ? STAGE_BYTES : 0);

#pragma unroll
        for (int kk = 0; kk < 2; ++kk) {
            uint32_t ah[2][4], al[2][4], bh[8][2], bl[8][2];
#pragma unroll
            for (int f = 0; f < 2; ++f) {
                const uint32_t ao = sb + ((a_row + f * 16) * KP + kk * 16 + a_col) * 2;
                ldm4(ah[f], ao);
                ldm4(al[f], ao + ARR_BYTES);
            }
#pragma unroll
            for (int p = 0; p < 4; ++p) {
                const uint32_t bo = sb + 2 * ARR_BYTES +
                                    ((b_row + p * 16) * KP + kk * 16 + b_col) * 2;
                uint32_t r[4];
                ldm4(r, bo);
                bh[2 * p][0] = r[0]; bh[2 * p][1] = r[1];
                bh[2 * p + 1][0] = r[2]; bh[2 * p + 1][1] = r[3];
                ldm4(r, bo + ARR_BYTES);
                bl[2 * p][0] = r[0]; bl[2 * p][1] = r[1];
                bl[2 * p + 1][0] = r[2]; bl[2 * p + 1][1] = r[3];
            }
#pragma unroll
            for (int mf = 0; mf < 2; ++mf)
#pragma unroll
                for (int nf = 0; nf < 8; ++nf) {
                    mma_bf16(acc[mf][nf], ah[mf], bh[nf]);
                    mma_bf16(acc[mf][nf], ah[mf], bl[nf]);
                    mma_bf16(acc[mf][nf], al[mf], bh[nf]);
                }
        }
        __syncthreads();                     // done reading stage i
    }

    // epilogue: acc -> out.  c0,c1:(m=l/4, n=2(l%4)); c2,c3:(m+8, same n)
    const int er = l >> 2, ec = (l & 3) << 1;
#pragma unroll
    for (int mf = 0; mf < 2; ++mf) {
        const int m0 = wm * 32 + mf * 16 + er;
#pragma unroll
        for (int nf = 0; nf < 8; ++nf) {
            const int n0 = wn * 64 + nf * 8 + ec;
            float* o0 = out + (size_t)m0 * ostride + n0;
            float* o1 = out + (size_t)(m0 + 8) * ostride + n0;
            o0[0] = acc[mf][nf][0]; o0[1] = acc[mf][nf][1];
            o1[0] = acc[mf][nf][2]; o1[1] = acc[mf][nf][3];
        }
    }
}

// ---------------- K1: split + transpose --------------------------------------
__global__ void __launch_bounds__(256) split_kernel(const float* __restrict__ X)
{
    __shared__ float tile[32][33];
    const int b = blockIdx.z;
    const int s0 = blockIdx.y * 32;
    const int d0 = blockIdx.x * 32;
    const int x = threadIdx.x, y0 = threadIdx.y;

#pragma unroll
    for (int yy = y0; yy < 32; yy += 8) {
        const size_t o = ((size_t)b * S + s0 + yy) * D + d0 + x;
        const float v = X[o];
        tile[yy][x] = v;
        const __nv_bfloat16 h = __float2bfloat16_rn(v);
        g_Xhi[o] = h;
        g_Xlo[o] = __float2bfloat16_rn(v - __bfloat162float(h));
    }
    __syncthreads();
#pragma unroll
    for (int yy = y0; yy < 32; yy += 8) {
        const float v = tile[x][yy];
        const size_t o = ((size_t)b * D + d0 + yy) * S + s0 + x;
        const __nv_bfloat16 h = __float2bfloat16_rn(v);
        g_XThi[o] = h;
        g_XTlo[o] = __float2bfloat16_rn(v - __bfloat162float(h));
    }
}

// ---------------- K2: scores -------------------------------------------------
__global__ void __launch_bounds__(256) scores_kernel()
{
    extern __shared__ char sm[];
    const int qt = blockIdx.x >> 4;
    const int kt = blockIdx.x & 15;
    if (kt > qt) return;                       // causal tile skip
    const int b = blockIdx.y;
    const int t = threadIdx.x;

    const __nv_bfloat16* Ah = g_Xhi + ((size_t)b * S + qt * 128) * D;
    const __nv_bfloat16* Al = g_Xlo + ((size_t)b * S + qt * 128) * D;
    const __nv_bfloat16* Bh = g_Xhi + ((size_t)b * S + kt * 128) * D;
    const __nv_bfloat16* Bl = g_Xlo + ((size_t)b * S + kt * 128) * D;
    float* out = g_S + ((size_t)b * S + qt * 128) * S + kt * 128;

    gemm_core(Ah, Al, Bh, Bl, D, D, D / 32, out, S, sm, t);
}

// ---------------- K3: softmax ------------------------------------------------
__global__ void __launch_bounds__(256) softmax_kernel(const int* __restrict__ mask)
{
    __shared__ float row[S];
    __shared__ float red[8];
    const int q = blockIdx.x;
    const int b = blockIdx.y;
    const int t = threadIdx.x, w = t >> 5, lane = t & 31;
    const int L = q + 1;
    const int Kmax = ((q >> 7) + 1) << 7;

    const float* Srow = g_S + ((size_t)b * S + q) * S;
    const int* mb = mask + (size_t)b * S;

    float lm = -3.0e38f;
    for (int k = t; k < L; k += 256) {
        float v = Srow[k] + (mb[k] ? 0.0f : NEGV);
        row[k] = v;
        lm = fmaxf(lm, v);
    }
#pragma unroll
    for (int d = 16; d > 0; d >>= 1) lm = fmaxf(lm, __shfl_xor_sync(0xffffffffu, lm, d));
    if (lane == 0) red[w] = lm;
    __syncthreads();
    const float m = fmaxf(fmaxf(fmaxf(red[0], red[1]), fmaxf(red[2], red[3])),
                          fmaxf(fmaxf(red[4], red[5]), fmaxf(red[6], red[7])));

    float ls = 0.0f;
    for (int k = t; k < L; k += 256) {
        const float e = expf(row[k] - m);
        row[k] = e;
        ls += e;
    }
#pragma unroll
    for (int d = 16; d > 0; d >>= 1) ls += __shfl_xor_sync(0xffffffffu, ls, d);
    __syncthreads();
    if (lane == 0) red[w] = ls;
    __syncthreads();
    const float sum = (red[0] + red[1]) + (red[2] + red[3]) +
                      (red[4] + red[5]) + (red[6] + red[7]);
    const float inv = 1.0f / sum;

    __nv_bfloat16* Ph = g_Phi + ((size_t)b * S + q) * S;
    __nv_bfloat16* Pl = g_Plo + ((size_t)b * S + q) * S;
    for (int k = t; k < L; k += 256) {
        const float p = row[k] * inv;
        const __nv_bfloat16 h = __float2bfloat16_rn(p);
        Ph[k] = h;
        Pl[k] = __float2bfloat16_rn(p - __bfloat162float(h));
    }
    const __nv_bfloat16 z = __float2bfloat16_rn(0.0f);
    for (int k = L + t; k < Kmax; k += 256) { Ph[k] = z; Pl[k] = z; }
}

// ---------------- K4: O = P V ------------------------------------------------
__global__ void __launch_bounds__(256) out_kernel(float* __restrict__ O)
{
    extern __shared__ char sm[];
    const int qt = blockIdx.x;
    const int dt = blockIdx.y;
    const int b = blockIdx.z;
    const int t = threadIdx.x;

    const __nv_bfloat16* Ah = g_Phi + ((size_t)b * S + qt * 128) * S;
    const __nv_bfloat16* Al = g_Plo + ((size_t)b * S + qt * 128) * S;
    const __nv_bfloat16* Bh = g_XThi + ((size_t)b * D + dt * 128) * S;
    const __nv_bfloat16* Bl = g_XTlo + ((size_t)b * D + dt * 128) * S;
    float* out = O + ((size_t)b * S + qt * 128) * D + dt * 128;

    const int nch = 4 * (qt + 1);              // causal K truncation (chunks of 32)
    gemm_core(Ah, Al, Bh, Bl, S, S, nch, out, D, sm, t);
}

} // namespace

extern "C" void kernel_launch(void* const* d_in, const int* in_sizes, int n_in,
                              void* d_out, int out_size)
{
    const float* X = (const float*)d_in[0];
    const int* mask = (const int*)d_in[1];
    float* O = (float*)d_out;

    cudaFuncSetAttribute(scores_kernel, cudaFuncAttributeMaxDynamicSharedMemorySize, SMEM_GEMM);
    cudaFuncSetAttribute(out_kernel, cudaFuncAttributeMaxDynamicSharedMemorySize, SMEM_GEMM);

    split_kernel<<<dim3(D / 32, S / 32, B), dim3(32, 8)>>>(X);
    scores_kernel<<<dim3(256, B), 256, SMEM_GEMM>>>();
    softmax_kernel<<<dim3(S, B), 256>>>(mask);
    out_kernel<<<dim3(16, 8, B), 256, SMEM_GEMM>>>(O);
}

// round 4
// speedup vs baseline: 6.3797x; 1.0631x over previous
#include <cuda_runtime.h>
#include <cuda_bf16.h>
#include <math.h>
#include <stdint.h>

// SimpleAttention B=4 S=2048 D=1024 fp32.
// bf16 hi/lo split fp32-emulated GEMMs on mma.sync (HMMA; harness compiles at
// compute_100 where tcgen05 is unavailable).
// R4: 2 CTAs/SM (launch_bounds), compact triangular scores grid, heavy-first
// out_kernel ordering, deeper cp.async overlap.

namespace {

constexpr int B = 4, S = 2048, D = 1024;
constexpr float NEGV = -1.0e9f;
constexpr int NQT = S / 128;                  // 16
constexpr int NTRI = NQT * (NQT + 1) / 2;     // 136

__device__ __align__(16) __nv_bfloat16 g_Xhi [(size_t)B * S * D];
__device__ __align__(16) __nv_bfloat16 g_Xlo [(size_t)B * S * D];
__device__ __align__(16) __nv_bfloat16 g_XThi[(size_t)B * D * S];
__device__ __align__(16) __nv_bfloat16 g_XTlo[(size_t)B * D * S];
__device__ __align__(16) float         g_S   [(size_t)B * S * S];
__device__ __align__(16) __nv_bfloat16 g_Phi [(size_t)B * S * S];
__device__ __align__(16) __nv_bfloat16 g_Plo [(size_t)B * S * S];

// ---------------- ptx helpers -------------------------------------------------
__device__ __forceinline__ uint32_t smem_u32(const void* p) {
    uint32_t a;
    asm("{ .reg .u64 t; cvta.to.shared.u64 t, %1; cvt.u32.u64 %0, t; }" : "=r"(a) : "l"(p));
    return a;
}
__device__ __forceinline__ void cpa16(uint32_t dst, const void* src) {
    asm volatile("cp.async.cg.shared.global [%0], [%1], 16;" :: "r"(dst), "l"(src) : "memory");
}
__device__ __forceinline__ void cpa_commit() {
    asm volatile("cp.async.commit_group;" ::: "memory");
}
template <int N> __device__ __forceinline__ void cpa_wait() {
    asm volatile("cp.async.wait_group %0;" :: "n"(N) : "memory");
}
__device__ __forceinline__ void ldm4(uint32_t* r, uint32_t addr) {
    asm volatile("ldmatrix.sync.aligned.m8n8.x4.shared.b16 {%0,%1,%2,%3}, [%4];"
                 : "=r"(r[0]), "=r"(r[1]), "=r"(r[2]), "=r"(r[3]) : "r"(addr));
}
__device__ __forceinline__ void mma_bf16(float* c, const uint32_t* a, const uint32_t* b) {
    asm volatile(
        "mma.sync.aligned.m16n8k16.row.col.f32.bf16.bf16.f32 "
        "{%0,%1,%2,%3}, {%4,%5,%6,%7}, {%8,%9}, {%0,%1,%2,%3};"
        : "+f"(c[0]), "+f"(c[1]), "+f"(c[2]), "+f"(c[3])
        : "r"(a[0]), "r"(a[1]), "r"(a[2]), "r"(a[3]), "r"(b[0]), "r"(b[1]));
}

// ---------------- GEMM core ---------------------------------------------------
// C[128,128] = (Ahi+Alo)[128,K] * (Bhi+Blo)[128,K]^T, lo*lo dropped.
// 8 warps as 4(m) x 2(n); warp tile 32x64; K-chunk 32; 2 smem stages.
constexpr int KP = 40;                      // padded row stride in bf16 (80B)
constexpr int ARR_BYTES = 128 * KP * 2;     // 10240
constexpr int STAGE_BYTES = 4 * ARR_BYTES;  // 40960: Ah, Al, Bh, Bl
constexpr int SMEM_GEMM = 2 * STAGE_BYTES;  // 81920

__device__ __forceinline__ void load_chunk(
    uint32_t stage_base,
    const __nv_bfloat16* __restrict__ Ah, const __nv_bfloat16* __restrict__ Al,
    const __nv_bfloat16* __restrict__ Bh, const __nv_bfloat16* __restrict__ Bl,
    int strideA, int strideB, int t)
{
#pragma unroll
    for (int j = 0; j < 8; ++j) {
        const int s = t + j * 256;           // 0..2047
        const int arr = s >> 9;              // 0..3
        const int rem = s & 511;
        const int row = rem >> 2;            // 0..127
        const int seg = rem & 3;             // 16B segment
        const __nv_bfloat16* base = (arr == 0) ? Ah : (arr == 1) ? Al : (arr == 2) ? Bh : Bl;
        const int stride = (arr < 2) ? strideA : strideB;
        cpa16(stage_base + arr * ARR_BYTES + row * (KP * 2) + seg * 16,
              base + (size_t)row * stride + seg * 8);
    }
}

__device__ __forceinline__ void gemm_core(
    const __nv_bfloat16* __restrict__ Ah, const __nv_bfloat16* __restrict__ Al,
    const __nv_bfloat16* __restrict__ Bh, const __nv_bfloat16* __restrict__ Bl,
    int strideA, int strideB, int nch,
    float* __restrict__ out, int ostride,
    char* sm, int t)
{
    const uint32_t smb = smem_u32(sm);
    const int w = t >> 5, l = t & 31;
    const int wm = w >> 1, wn = w & 1;       // 4 x 2 warps

    float acc[2][8][4];
#pragma unroll
    for (int i = 0; i < 2; ++i)
#pragma unroll
        for (int j = 0; j < 8; ++j)
#pragma unroll
            for (int k = 0; k < 4; ++k) acc[i][j][k] = 0.f;

    const int a_row = wm * 32 + (l & 15);
    const int a_col = (l >> 4) << 3;
    const int b_row = wn * 64 + (l & 7) + (((l >> 4) & 1) << 3);
    const int b_col = ((l >> 3) & 1) << 3;

    load_chunk(smb, Ah, Al, Bh, Bl, strideA, strideB, t);
    cpa_commit();

    for (int i = 0; i < nch; ++i) {
        if (i + 1 < nch) {
            // stage (i+1)&1 was released at the trailing sync of iter i-1
            load_chunk(smb + (((i + 1) & 1) ? STAGE_BYTES : 0),
                       Ah + (i + 1) * 32, Al + (i + 1) * 32,
                       Bh + (i + 1) * 32, Bl + (i + 1) * 32,
                       strideA, strideB, t);
            cpa_commit();
            cpa_wait<1>();                   // chunk i resident
        } else {
            cpa_wait<0>();
        }
        __syncthreads();
        const uint32_t sb = smb + ((i & 1) ? STAGE_BYTES : 0);

#pragma unroll
        for (int kk = 0; kk < 2; ++kk) {
            uint32_t ah[2][4], al[2][4];
#pragma unroll
            for (int f = 0; f < 2; ++f) {
                const uint32_t ao = sb + ((a_row + f * 16) * KP + kk * 16 + a_col) * 2;
                ldm4(ah[f], ao);
                ldm4(al[f], ao + ARR_BYTES);
            }
            // B fragments loaded per 16-col pair to cap live registers (~88)
#pragma unroll
            for (int p = 0; p < 4; ++p) {
                const uint32_t bo = sb + 2 * ARR_BYTES +
                                    ((b_row + p * 16) * KP + kk * 16 + b_col) * 2;
                uint32_t rh[4], rl[4];
                ldm4(rh, bo);
                ldm4(rl, bo + ARR_BYTES);
#pragma unroll
                for (int h = 0; h < 2; ++h) {
                    const int nf = 2 * p + h;
                    mma_bf16(acc[0][nf], ah[0], rh + 2 * h);
                    mma_bf16(acc[1][nf], ah[1], rh + 2 * h);
                    mma_bf16(acc[0][nf], ah[0], rl + 2 * h);
                    mma_bf16(acc[1][nf], ah[1], rl + 2 * h);
                    mma_bf16(acc[0][nf], al[0], rh + 2 * h);
                    mma_bf16(acc[1][nf], al[1], rh + 2 * h);
                }
            }
        }
        __syncthreads();                     // done reading stage i
    }

    const int er = l >> 2, ec = (l & 3) << 1;
#pragma unroll
    for (int mf = 0; mf < 2; ++mf) {
        const int m0 = wm * 32 + mf * 16 + er;
#pragma unroll
        for (int nf = 0; nf < 8; ++nf) {
            const int n0 = wn * 64 + nf * 8 + ec;
            *reinterpret_cast<float2*>(out + (size_t)m0 * ostride + n0) =
                make_float2(acc[mf][nf][0], acc[mf][nf][1]);
            *reinterpret_cast<float2*>(out + (size_t)(m0 + 8) * ostride + n0) =
                make_float2(acc[mf][nf][2], acc[mf][nf][3]);
        }
    }
}

// ---------------- K1: split + transpose --------------------------------------
__global__ void __launch_bounds__(256) split_kernel(const float* __restrict__ X)
{
    __shared__ float tile[32][33];
    const int b = blockIdx.z;
    const int s0 = blockIdx.y * 32;
    const int d0 = blockIdx.x * 32;
    const int x = threadIdx.x, y0 = threadIdx.y;

#pragma unroll
    for (int yy = y0; yy < 32; yy += 8) {
        const size_t o = ((size_t)b * S + s0 + yy) * D + d0 + x;
        const float v = X[o];
        tile[yy][x] = v;
        const __nv_bfloat16 h = __float2bfloat16_rn(v);
        g_Xhi[o] = h;
        g_Xlo[o] = __float2bfloat16_rn(v - __bfloat162float(h));
    }
    __syncthreads();
#pragma unroll
    for (int yy = y0; yy < 32; yy += 8) {
        const float v = tile[x][yy];
        const size_t o = ((size_t)b * D + d0 + yy) * S + s0 + x;
        const __nv_bfloat16 h = __float2bfloat16_rn(v);
        g_XThi[o] = h;
        g_XTlo[o] = __float2bfloat16_rn(v - __bfloat162float(h));
    }
}

// ---------------- K2: scores (compact lower-triangular grid) ------------------
__global__ void __launch_bounds__(256, 2) scores_kernel()
{
    extern __shared__ char sm[];
    const int idx = blockIdx.x;              // 0..NTRI-1
    int qt = (int)((sqrtf(8.0f * (float)idx + 1.0f) - 1.0f) * 0.5f);
    while ((qt + 1) * (qt + 2) / 2 <= idx) ++qt;
    while (qt * (qt + 1) / 2 > idx) --qt;
    const int kt = idx - qt * (qt + 1) / 2;
    const int b = blockIdx.y;
    const int t = threadIdx.x;

    const __nv_bfloat16* Ah = g_Xhi + ((size_t)b * S + qt * 128) * D;
    const __nv_bfloat16* Al = g_Xlo + ((size_t)b * S + qt * 128) * D;
    const __nv_bfloat16* Bh = g_Xhi + ((size_t)b * S + kt * 128) * D;
    const __nv_bfloat16* Bl = g_Xlo + ((size_t)b * S + kt * 128) * D;
    float* out = g_S + ((size_t)b * S + qt * 128) * S + kt * 128;

    gemm_core(Ah, Al, Bh, Bl, D, D, D / 32, out, S, sm, t);
}

// ---------------- K3: softmax ------------------------------------------------
__global__ void __launch_bounds__(256) softmax_kernel(const int* __restrict__ mask)
{
    __shared__ float row[S];
    __shared__ float red[8];
    const int q = blockIdx.x;
    const int b = blockIdx.y;
    const int t = threadIdx.x, w = t >> 5, lane = t & 31;
    const int L = q + 1;
    const int Kmax = ((q >> 7) + 1) << 7;

    const float* Srow = g_S + ((size_t)b * S + q) * S;
    const int* mb = mask + (size_t)b * S;

    float lm = -3.0e38f;
    for (int k = t; k < L; k += 256) {
        float v = Srow[k] + (mb[k] ? 0.0f : NEGV);
        row[k] = v;
        lm = fmaxf(lm, v);
    }
#pragma unroll
    for (int d = 16; d > 0; d >>= 1) lm = fmaxf(lm, __shfl_xor_sync(0xffffffffu, lm, d));
    if (lane == 0) red[w] = lm;
    __syncthreads();
    const float m = fmaxf(fmaxf(fmaxf(red[0], red[1]), fmaxf(red[2], red[3])),
                          fmaxf(fmaxf(red[4], red[5]), fmaxf(red[6], red[7])));

    float ls = 0.0f;
    for (int k = t; k < L; k += 256) {
        const float e = expf(row[k] - m);
        row[k] = e;
        ls += e;
    }
#pragma unroll
    for (int d = 16; d > 0; d >>= 1) ls += __shfl_xor_sync(0xffffffffu, ls, d);
    __syncthreads();
    if (lane == 0) red[w] = ls;
    __syncthreads();
    const float sum = (red[0] + red[1]) + (red[2] + red[3]) +
                      (red[4] + red[5]) + (red[6] + red[7]);
    const float inv = 1.0f / sum;

    __nv_bfloat16* Ph = g_Phi + ((size_t)b * S + q) * S;
    __nv_bfloat16* Pl = g_Plo + ((size_t)b * S + q) * S;
    for (int k = t; k < L; k += 256) {
        const float p = row[k] * inv;
        const __nv_bfloat16 h = __float2bfloat16_rn(p);
        Ph[k] = h;
        Pl[k] = __float2bfloat16_rn(p - __bfloat162float(h));
    }
    const __nv_bfloat16 z = __float2bfloat16_rn(0.0f);
    for (int k = L + t; k < Kmax; k += 256) { Ph[k] = z; Pl[k] = z; }
}

// ---------------- K4: O = P V (heavy tiles first) -----------------------------
__global__ void __launch_bounds__(256, 2) out_kernel(float* __restrict__ O)
{
    extern __shared__ char sm[];
    const int qt = NQT - 1 - blockIdx.x;     // heavy-first
    const int dt = blockIdx.y;
    const int b = blockIdx.z;
    const int t = threadIdx.x;

    const __nv_bfloat16* Ah = g_Phi + ((size_t)b * S + qt * 128) * S;
    const __nv_bfloat16* Al = g_Plo + ((size_t)b * S + qt * 128) * S;
    const __nv_bfloat16* Bh = g_XThi + ((size_t)b * D + dt * 128) * S;
    const __nv_bfloat16* Bl = g_XTlo + ((size_t)b * D + dt * 128) * S;
    float* out = O + ((size_t)b * S + qt * 128) * D + dt * 128;

    const int nch = 4 * (qt + 1);            // causal K truncation
    gemm_core(Ah, Al, Bh, Bl, S, S, nch, out, D, sm, t);
}

} // namespace

extern "C" void kernel_launch(void* const* d_in, const int* in_sizes, int n_in,
                              void* d_out, int out_size)
{
    const float* X = (const float*)d_in[0];
    const int* mask = (const int*)d_in[1];
    float* O = (float*)d_out;

    cudaFuncSetAttribute(scores_kernel, cudaFuncAttributeMaxDynamicSharedMemorySize, SMEM_GEMM);
    cudaFuncSetAttribute(out_kernel, cudaFuncAttributeMaxDynamicSharedMemorySize, SMEM_GEMM);

    split_kernel<<<dim3(D / 32, S / 32, B), dim3(32, 8)>>>(X);
    scores_kernel<<<dim3(NTRI, B), 256, SMEM_GEMM>>>();
    softmax_kernel<<<dim3(S, B), 256>>>(mask);
    out_kernel<<<dim3(NQT, 8, B), 256, SMEM_GEMM>>>(O);
}